// round 7
// baseline (speedup 1.0000x reference)
#include <cuda_runtime.h>
#include <cstddef>

#define N_NODES 100000
#define N_EDGES 640000
#define DIM 128
#define ALPHA 0.3f
#define BIN_CAP 64                // P(Poisson(6.4) >= 64) ~ 1e-40: safe hard bound

#define NTHREADS 256
#define BLOCKS_PER_SM 3
#define NUM_SMS 148               // GB300 has 152; 148*3 blocks resident even on 148
#define NBLOCKS (NUM_SMS * BLOCKS_PER_SM)          // 444
#define NWARPS_TOTAL (NBLOCKS * (NTHREADS / 32))   // 3552

// ── Allocation-free scratch ─────────────────────────────────────────────
// g_count: zero-initialized .bss at module load; phase B self-cleans it so
// every subsequent launch (correctness run + every graph replay) starts at 0.
__device__ int  g_count[N_NODES];
__device__ int2 g_bins[(size_t)N_NODES * BIN_CAP];  // {edge_id, src} per dst bin
__device__ unsigned g_bar_count = 0;
__device__ unsigned g_bar_gen   = 0;

// Ticket + generation grid barrier. All NBLOCKS are resident (launch_bounds
// guarantees 3 blocks/SM fit), so spinning is deadlock-free. State returns to
// {count=0} after each use; gen comparisons are relative, so replays are fine.
__device__ __forceinline__ void grid_barrier() {
    __syncthreads();
    if (threadIdx.x == 0) {
        volatile unsigned* genp = &g_bar_gen;
        unsigned mygen = *genp;
        __threadfence();                               // release phase-A writes
        unsigned ticket = atomicAdd(&g_bar_count, 1u);
        if (ticket == NBLOCKS - 1) {
            g_bar_count = 0;
            __threadfence();
            atomicAdd(&g_bar_gen, 1u);
        } else {
            while (*genp == mygen) { __nanosleep(64); }
        }
        __threadfence();                               // acquire
    }
    __syncthreads();
}

__global__ void __launch_bounds__(NTHREADS, BLOCKS_PER_SM)
fused_kernel(const float* __restrict__ src_emb,
             const float* __restrict__ dst_emb,
             const float* __restrict__ edge_emb,
             const int*   __restrict__ src_idx,
             const int*   __restrict__ dst_idx,
             float*       __restrict__ out) {
    const int tid      = blockIdx.x * NTHREADS + threadIdx.x;
    const int nthreads = NBLOCKS * NTHREADS;

    // ── Phase A: bin edges by dst (counts start at 0: .bss / self-cleaned) ──
    for (int e = tid; e < N_EDGES; e += nthreads) {
        int d = __ldg(dst_idx + e);
        int s = __ldg(src_idx + e);
        int rank = atomicAdd(&g_count[d], 1);
        g_bins[(size_t)d * BIN_CAP + rank] = make_int2(e, s);
    }

    grid_barrier();

    // ── Phase B: one warp per node, clamped unroll-4 (8 LDG.128 in flight
    //    every iteration, no low-MLP tail), fused mean+lerp+zero, 1 store. ──
    const int warp = tid >> 5;
    const int lane = tid & 31;

    for (int n = warp; n < N_NODES; n += NWARPS_TOTAL) {
        int deg = g_count[n];
        if (lane == 0) g_count[n] = 0;          // self-clean for next launch
        const int2* bin = g_bins + (size_t)n * BIN_CAP;
        size_t off = (size_t)n * DIM + (size_t)lane * 4;

        if (deg == 0) {
            *reinterpret_cast<float4*>(out + off) = make_float4(0.f, 0.f, 0.f, 0.f);
            continue;
        }

        float4 de = __ldcs(reinterpret_cast<const float4*>(dst_emb + off));
        float4 acc = make_float4(0.f, 0.f, 0.f, 0.f);

        for (int j = 0; j < deg; j += 4) {
            int j1 = min(j + 1, deg - 1);
            int j2 = min(j + 2, deg - 1);
            int j3 = min(j + 3, deg - 1);
            float w1 = (j + 1 < deg) ? 1.f : 0.f;
            float w2 = (j + 2 < deg) ? 1.f : 0.f;
            float w3 = (j + 3 < deg) ? 1.f : 0.f;

            int2 r0 = __ldg(bin + j);
            int2 r1 = __ldg(bin + j1);
            int2 r2 = __ldg(bin + j2);
            int2 r3 = __ldg(bin + j3);

            float4 a0 = __ldg (reinterpret_cast<const float4*>(src_emb  + (size_t)r0.y * DIM) + lane);
            float4 b0 = __ldcs(reinterpret_cast<const float4*>(edge_emb + (size_t)r0.x * DIM) + lane);
            float4 a1 = __ldg (reinterpret_cast<const float4*>(src_emb  + (size_t)r1.y * DIM) + lane);
            float4 b1 = __ldcs(reinterpret_cast<const float4*>(edge_emb + (size_t)r1.x * DIM) + lane);
            float4 a2 = __ldg (reinterpret_cast<const float4*>(src_emb  + (size_t)r2.y * DIM) + lane);
            float4 b2 = __ldcs(reinterpret_cast<const float4*>(edge_emb + (size_t)r2.x * DIM) + lane);
            float4 a3 = __ldg (reinterpret_cast<const float4*>(src_emb  + (size_t)r3.y * DIM) + lane);
            float4 b3 = __ldcs(reinterpret_cast<const float4*>(edge_emb + (size_t)r3.x * DIM) + lane);

            acc.x += (a0.x + b0.x) + w1 * (a1.x + b1.x) + w2 * (a2.x + b2.x) + w3 * (a3.x + b3.x);
            acc.y += (a0.y + b0.y) + w1 * (a1.y + b1.y) + w2 * (a2.y + b2.y) + w3 * (a3.y + b3.y);
            acc.z += (a0.z + b0.z) + w1 * (a1.z + b1.z) + w2 * (a2.z + b2.z) + w3 * (a3.z + b3.z);
            acc.w += (a0.w + b0.w) + w1 * (a1.w + b1.w) + w2 * (a2.w + b2.w) + w3 * (a3.w + b3.w);
        }

        float inv = (1.0f - ALPHA) / (float)deg;
        float4 r;
        r.x = ALPHA * de.x + acc.x * inv;
        r.y = ALPHA * de.y + acc.y * inv;
        r.z = ALPHA * de.z + acc.z * inv;
        r.w = ALPHA * de.w + acc.w * inv;
        *reinterpret_cast<float4*>(out + off) = r;
    }
}

extern "C" void kernel_launch(void* const* d_in, const int* in_sizes, int n_in,
                              void* d_out, int out_size) {
    const float* src_emb  = (const float*)d_in[0];
    const float* dst_emb  = (const float*)d_in[1];
    const float* edge_emb = (const float*)d_in[2];
    const int*   src_idx  = (const int*)d_in[3];
    const int*   dst_idx  = (const int*)d_in[4];
    float* out = (float*)d_out;

    fused_kernel<<<NBLOCKS, NTHREADS>>>(src_emb, dst_emb, edge_emb,
                                        src_idx, dst_idx, out);
}

// round 8
// speedup vs baseline: 2.8932x; 2.8932x over previous
#include <cuda_runtime.h>
#include <cstddef>

#define N_NODES 100000
#define N_EDGES 640000
#define DIM 128
#define ALPHA 0.3f
#define BIN_CAP 64            // P(Poisson(6.4) >= 64) ~ 1e-40: safe hard bound

// ── Allocation-free scratch ─────────────────────────────────────────────
__device__ int  g_count[N_NODES];                       // cursor, then degree
__device__ int2 g_bins[(size_t)N_NODES * BIN_CAP];      // {edge_id, src} per dst bin

// K1: bin edges by dst. Cursor atomics spread over 100k addresses (avg 6.4
// per address) — near the L2 atomic-ALU spread floor. Packs {eid, src} so
// the gather loop needs one 8B load per edge, no further indirection.
__global__ void bin_edges(const int* __restrict__ src_idx,
                          const int* __restrict__ dst_idx) {
    int e = blockIdx.x * blockDim.x + threadIdx.x;
    if (e >= N_EDGES) return;
    int d = dst_idx[e];
    int s = src_idx[e];
    int rank = atomicAdd(&g_count[d], 1);
    g_bins[(size_t)d * BIN_CAP + rank] = make_int2(e, s);
}
// After K1, g_count[n] == degree(n).

// K2: one warp per node. Unroll-4 main loop (8 independent LDG.128 in
// flight), plain tail. launch_bounds(256,5) caps regs at 50 -> 40 resident
// warps/SM (vs ~32 uncapped): this kernel is in-flight-bytes bound, so
// occupancy x MLP is the product that sets DRAM throughput.
__global__ void __launch_bounds__(256, 5)
gather_finalize(const float* __restrict__ src_emb,
                const float* __restrict__ dst_emb,
                const float* __restrict__ edge_emb,
                float*       __restrict__ out) {
    int g    = blockIdx.x * blockDim.x + threadIdx.x;
    int n    = g >> 5;
    int lane = g & 31;
    if (n >= N_NODES) return;

    int deg = g_count[n];
    const int2* bin = g_bins + (size_t)n * BIN_CAP;
    size_t off = (size_t)n * DIM + (size_t)lane * 4;

    if (deg == 0) {
        *reinterpret_cast<float4*>(out + off) = make_float4(0.f, 0.f, 0.f, 0.f);
        return;
    }

    // Independent of the gather chain: hoist to overlap.
    float4 de = __ldcs(reinterpret_cast<const float4*>(dst_emb + off));

    float4 acc = make_float4(0.f, 0.f, 0.f, 0.f);
    int j = 0;
    for (; j + 3 < deg; j += 4) {
        int2 r0 = __ldg(bin + j);
        int2 r1 = __ldg(bin + j + 1);
        int2 r2 = __ldg(bin + j + 2);
        int2 r3 = __ldg(bin + j + 3);
        float4 a0 = __ldg (reinterpret_cast<const float4*>(src_emb  + (size_t)r0.y * DIM) + lane);
        float4 b0 = __ldcs(reinterpret_cast<const float4*>(edge_emb + (size_t)r0.x * DIM) + lane);
        float4 a1 = __ldg (reinterpret_cast<const float4*>(src_emb  + (size_t)r1.y * DIM) + lane);
        float4 b1 = __ldcs(reinterpret_cast<const float4*>(edge_emb + (size_t)r1.x * DIM) + lane);
        float4 a2 = __ldg (reinterpret_cast<const float4*>(src_emb  + (size_t)r2.y * DIM) + lane);
        float4 b2 = __ldcs(reinterpret_cast<const float4*>(edge_emb + (size_t)r2.x * DIM) + lane);
        float4 a3 = __ldg (reinterpret_cast<const float4*>(src_emb  + (size_t)r3.y * DIM) + lane);
        float4 b3 = __ldcs(reinterpret_cast<const float4*>(edge_emb + (size_t)r3.x * DIM) + lane);
        acc.x += ((a0.x + b0.x) + (a1.x + b1.x)) + ((a2.x + b2.x) + (a3.x + b3.x));
        acc.y += ((a0.y + b0.y) + (a1.y + b1.y)) + ((a2.y + b2.y) + (a3.y + b3.y));
        acc.z += ((a0.z + b0.z) + (a1.z + b1.z)) + ((a2.z + b2.z) + (a3.z + b3.z));
        acc.w += ((a0.w + b0.w) + (a1.w + b1.w)) + ((a2.w + b2.w) + (a3.w + b3.w));
    }
    if (j + 1 < deg) {                       // 2-edge step for the tail
        int2 r0 = __ldg(bin + j);
        int2 r1 = __ldg(bin + j + 1);
        float4 a0 = __ldg (reinterpret_cast<const float4*>(src_emb  + (size_t)r0.y * DIM) + lane);
        float4 b0 = __ldcs(reinterpret_cast<const float4*>(edge_emb + (size_t)r0.x * DIM) + lane);
        float4 a1 = __ldg (reinterpret_cast<const float4*>(src_emb  + (size_t)r1.y * DIM) + lane);
        float4 b1 = __ldcs(reinterpret_cast<const float4*>(edge_emb + (size_t)r1.x * DIM) + lane);
        acc.x += (a0.x + b0.x) + (a1.x + b1.x);
        acc.y += (a0.y + b0.y) + (a1.y + b1.y);
        acc.z += (a0.z + b0.z) + (a1.z + b1.z);
        acc.w += (a0.w + b0.w) + (a1.w + b1.w);
        j += 2;
    }
    if (j < deg) {
        int2 r0 = __ldg(bin + j);
        float4 a0 = __ldg (reinterpret_cast<const float4*>(src_emb  + (size_t)r0.y * DIM) + lane);
        float4 b0 = __ldcs(reinterpret_cast<const float4*>(edge_emb + (size_t)r0.x * DIM) + lane);
        acc.x += a0.x + b0.x;
        acc.y += a0.y + b0.y;
        acc.z += a0.z + b0.z;
        acc.w += a0.w + b0.w;
    }

    float inv = (1.0f - ALPHA) / (float)deg;
    float4 r;
    r.x = ALPHA * de.x + acc.x * inv;
    r.y = ALPHA * de.y + acc.y * inv;
    r.z = ALPHA * de.z + acc.z * inv;
    r.w = ALPHA * de.w + acc.w * inv;
    *reinterpret_cast<float4*>(out + off) = r;
}

extern "C" void kernel_launch(void* const* d_in, const int* in_sizes, int n_in,
                              void* d_out, int out_size) {
    const float* src_emb  = (const float*)d_in[0];
    const float* dst_emb  = (const float*)d_in[1];
    const float* edge_emb = (const float*)d_in[2];
    const int*   src_idx  = (const int*)d_in[3];
    const int*   dst_idx  = (const int*)d_in[4];
    float* out = (float*)d_out;

    int* d_count;
    cudaGetSymbolAddress((void**)&d_count, g_count);
    cudaMemsetAsync(d_count, 0, N_NODES * sizeof(int));    // graph-legal, no launch

    bin_edges<<<(N_EDGES + 255) / 256, 256>>>(src_idx, dst_idx);

    {
        long long total = (long long)N_NODES * 32;   // one warp per node
        int blocks = (int)((total + 255) / 256);
        gather_finalize<<<blocks, 256>>>(src_emb, dst_emb, edge_emb, out);
    }
}